// round 6
// baseline (speedup 1.0000x reference)
#include <cuda_runtime.h>
#include <cuda_bf16.h>
#include <math.h>

#define T_STEPS 128
#define NE 64
#define NA 8
#define OBS 64
#define D 128
#define CH 128
#define VH 256
#define BATCH 512           // NE*NA
#define TB (T_STEPS*BATCH)  // 65536
#define ITERS 2

// ---------------- scratch (static device arrays: allocation-free) -------------
__device__ float g_emb1[TB * D];
__device__ float g_emb2[TB * D];
__device__ float g_gi[TB * 3 * D];
__device__ float g_e[TB * D];
__device__ float g_aiaj[TB * 2 * CH];   // merged [ai | aj], row stride 256
__device__ float g_ctx[TB * D];
__device__ float g_d1[TB * D];
__device__ float g_v1[TB * VH];
__device__ float g_v2[TB * VH];
__device__ unsigned char g_dmask[TB];
__device__ int g_dflag;   // 0 = uint8/bool, 1 = float32, 2 = int32

// ---------------- dones dtype detection + canonicalization --------------------
__global__ void detect_dones_kernel(const unsigned char* __restrict__ p, int n)
{
    __shared__ int s_nonbin, s_off4;
    if (threadIdx.x == 0) { s_nonbin = 0; s_off4 = 0; }
    __syncthreads();
    int nb = 0, o4 = 0;
    for (int i = threadIdx.x; i < n; i += blockDim.x) {
        const unsigned char b = p[i];
        if (b > 1) nb = 1;
        else if (b == 1 && (i & 3)) o4 = 1;
    }
    if (nb) atomicOr(&s_nonbin, 1);
    if (o4) atomicOr(&s_off4, 1);
    __syncthreads();
    if (threadIdx.x == 0)
        g_dflag = s_nonbin ? 1 : (s_off4 ? 0 : 2);
}

__global__ void conv_dones_kernel(const void* __restrict__ p, int n)
{
    const int i = blockIdx.x * blockDim.x + threadIdx.x;
    if (i >= n) return;
    const int f = g_dflag;
    unsigned char m;
    if (f == 1)      m = (((const float*)p)[i] != 0.f);
    else if (f == 2) m = (((const int*)p)[i] != 0);
    else             m = (((const unsigned char*)p)[i] != 0);
    g_dmask[i] = m;
}

// ---------------- BF16 tensor-core GEMM (2-way split, 3 products ~ fp32) -------
// C[M,N] = epilogue( A[M,K] @ B[K,N] (+ A2 @ B2) + bias )
// flags: 1 relu | 2 dual-source | 4 resid+alive | 8 B column-split (Bm cols 0..127, B2 cols 128..255)
// ldb = row stride of B matrices (may differ from N).
#define BM 128
#define BN 128
#define BK 16
#define AST 12      // As row stride in u32 (8 used + pad) -> conflict-free frag reads
#define BST 136     // Bs row stride in u32 -> conflict-free frag reads

__device__ __forceinline__ unsigned pack_bf16(float lo_elem, float hi_elem)
{
    unsigned d;
    asm("cvt.rn.bf16x2.f32 %0, %1, %2;" : "=r"(d) : "f"(hi_elem), "f"(lo_elem));
    return d;
}

__device__ __forceinline__ void mma_bf16(float* c, const unsigned* a, const unsigned* b)
{
    asm volatile(
        "mma.sync.aligned.m16n8k16.row.col.f32.bf16.bf16.f32 "
        "{%0,%1,%2,%3}, {%4,%5,%6,%7}, {%8,%9}, {%0,%1,%2,%3};"
        : "+f"(c[0]), "+f"(c[1]), "+f"(c[2]), "+f"(c[3])
        : "r"(a[0]), "r"(a[1]), "r"(a[2]), "r"(a[3]), "r"(b[0]), "r"(b[1]));
}

__global__ __launch_bounds__(256) void tgemm_kernel(
    int M, int N, int K, int ldb,
    const float* __restrict__ A, const float* __restrict__ Bm,
    const float* __restrict__ A2, const float* __restrict__ B2,
    const float* __restrict__ bias, float* __restrict__ Cout,
    int flags, const float* __restrict__ Ein,
    const unsigned char* __restrict__ dones)
{
    __shared__ __align__(16) unsigned As[2][2][BM * AST];  // [buf][hi/lo][m][kpair]
    __shared__ __align__(16) unsigned Bs[2][2][(BK / 2) * BST]; // [buf][hi/lo][kpair][n]

    const int tid  = threadIdx.x;
    const int brow = blockIdx.y * BM;
    const int bcol = blockIdx.x * BN;
    const int w    = tid >> 5, lane = tid & 31;
    const int gid  = lane >> 2, tig = lane & 3;
    const int wm   = (w & 1) * 64;
    const int wn   = (w >> 1) * 32;

    const int arow0 = tid >> 2;          // 0..63 (+64 on pass 1)
    const int afc   = (tid & 3) * 4;     // k-col within tile (0,4,8,12)
    const int brw   = tid >> 5;          // k-pair row 0..7
    const int bfc   = (tid & 31) * 4;    // n-col within tile

    float acc[4][4][4];
#pragma unroll
    for (int i = 0; i < 4; i++)
#pragma unroll
        for (int j = 0; j < 4; j++)
#pragma unroll
            for (int q = 0; q < 4; q++) acc[i][j][q] = 0.f;

    const int nsrc = (flags & 2) ? 2 : 1;
    const int tilesPerSrc = K / BK;
    const int ntiles = nsrc * tilesPerSrc;

    float4 rA[2], rB[2];

    auto loadTile = [&](int t) {
        const int s  = (t >= tilesPerSrc) ? 1 : 0;
        const int k0 = (t - s * tilesPerSrc) * BK;
        const float* Ap = s ? A2 : A;
        const float* Bp;
        int bc;
        if (flags & 8) { Bp = (bcol >= BN) ? B2 : Bm; bc = 0; }
        else           { Bp = s ? B2 : Bm;            bc = bcol; }
        rA[0] = *(const float4*)(Ap + (size_t)(brow + arow0) * K + k0 + afc);
        rA[1] = *(const float4*)(Ap + (size_t)(brow + arow0 + 64) * K + k0 + afc);
        rB[0] = *(const float4*)(Bp + (size_t)(k0 + 2 * brw) * ldb + bc + bfc);
        rB[1] = *(const float4*)(Bp + (size_t)(k0 + 2 * brw + 1) * ldb + bc + bfc);
    };

    auto storeTile = [&](int buf) {
        // A: split hi/lo, pack k pairs
#pragma unroll
        for (int p = 0; p < 2; p++) {
            const float4 v = rA[p];
            const float h0 = __bfloat162float(__float2bfloat16(v.x));
            const float h1 = __bfloat162float(__float2bfloat16(v.y));
            const float h2 = __bfloat162float(__float2bfloat16(v.z));
            const float h3 = __bfloat162float(__float2bfloat16(v.w));
            const int base = (arow0 + p * 64) * AST + (tid & 3) * 2;
            *(uint2*)&As[buf][0][base] = make_uint2(pack_bf16(h0, h1), pack_bf16(h2, h3));
            *(uint2*)&As[buf][1][base] = make_uint2(pack_bf16(v.x - h0, v.y - h1),
                                                    pack_bf16(v.z - h2, v.w - h3));
        }
        // B: rows (2*brw, 2*brw+1) pack across k
        {
            const float4 va = rB[0], vb = rB[1];
            float ha0 = __bfloat162float(__float2bfloat16(va.x));
            float ha1 = __bfloat162float(__float2bfloat16(va.y));
            float ha2 = __bfloat162float(__float2bfloat16(va.z));
            float ha3 = __bfloat162float(__float2bfloat16(va.w));
            float hb0 = __bfloat162float(__float2bfloat16(vb.x));
            float hb1 = __bfloat162float(__float2bfloat16(vb.y));
            float hb2 = __bfloat162float(__float2bfloat16(vb.z));
            float hb3 = __bfloat162float(__float2bfloat16(vb.w));
            const int base = brw * BST + bfc;
            *(uint4*)&Bs[buf][0][base] = make_uint4(
                pack_bf16(ha0, hb0), pack_bf16(ha1, hb1),
                pack_bf16(ha2, hb2), pack_bf16(ha3, hb3));
            *(uint4*)&Bs[buf][1][base] = make_uint4(
                pack_bf16(va.x - ha0, vb.x - hb0), pack_bf16(va.y - ha1, vb.y - hb1),
                pack_bf16(va.z - ha2, vb.z - hb2), pack_bf16(va.w - ha3, vb.w - hb3));
        }
    };

    loadTile(0);
    storeTile(0);
    __syncthreads();

    for (int t = 0; t < ntiles; t++) {
        if (t + 1 < ntiles) loadTile(t + 1);

        const unsigned* Ash = As[t & 1][0];
        const unsigned* Asl = As[t & 1][1];
        const unsigned* Bsh = Bs[t & 1][0];
        const unsigned* Bsl = Bs[t & 1][1];

        unsigned bh[4][2], bl[4][2];
#pragma unroll
        for (int ns = 0; ns < 4; ns++) {
            const int n = wn + ns * 8 + gid;
            bh[ns][0] = Bsh[tig * BST + n];
            bh[ns][1] = Bsh[(tig + 4) * BST + n];
            bl[ns][0] = Bsl[tig * BST + n];
            bl[ns][1] = Bsl[(tig + 4) * BST + n];
        }
#pragma unroll
        for (int ms = 0; ms < 4; ms++) {
            const int m0 = wm + ms * 16 + gid;
            unsigned ah[4], al[4];
            ah[0] = Ash[m0 * AST + tig];
            ah[1] = Ash[(m0 + 8) * AST + tig];
            ah[2] = Ash[m0 * AST + tig + 4];
            ah[3] = Ash[(m0 + 8) * AST + tig + 4];
            al[0] = Asl[m0 * AST + tig];
            al[1] = Asl[(m0 + 8) * AST + tig];
            al[2] = Asl[m0 * AST + tig + 4];
            al[3] = Asl[(m0 + 8) * AST + tig + 4];
#pragma unroll
            for (int ns = 0; ns < 4; ns++) {
                mma_bf16(acc[ms][ns], ah, bh[ns]);   // hi*hi
                mma_bf16(acc[ms][ns], ah, bl[ns]);   // hi*lo
                mma_bf16(acc[ms][ns], al, bh[ns]);   // lo*hi
            }
        }

        if (t + 1 < ntiles) {
            storeTile((t + 1) & 1);   // writes other buffer; safe pre-sync
            __syncthreads();
        }
    }

    // epilogue
    const bool hasb   = (bias != nullptr);
    const bool resid  = (flags & 4);
    const bool dorelu = (flags & 5);
#pragma unroll
    for (int ms = 0; ms < 4; ms++) {
        const int r0 = brow + wm + ms * 16 + gid;
        const int r1 = r0 + 8;
        float alive0 = 1.f, alive1 = 1.f;
        const float *E0 = nullptr, *E1 = nullptr;
        if (resid) {
            alive0 = dones[r0] ? 0.f : 1.f;
            alive1 = dones[r1] ? 0.f : 1.f;
            E0 = Ein + (size_t)r0 * N;
            E1 = Ein + (size_t)r1 * N;
        }
#pragma unroll
        for (int ns = 0; ns < 4; ns++) {
            const int c = bcol + wn + ns * 8 + tig * 2;
            float b0 = 0.f, b1 = 0.f;
            if (hasb) { b0 = bias[c]; b1 = bias[c + 1]; }
            float v0 = acc[ms][ns][0] + b0;
            float v1 = acc[ms][ns][1] + b1;
            float v2 = acc[ms][ns][2] + b0;
            float v3 = acc[ms][ns][3] + b1;
            if (dorelu) {
                v0 = fmaxf(v0, 0.f); v1 = fmaxf(v1, 0.f);
                v2 = fmaxf(v2, 0.f); v3 = fmaxf(v3, 0.f);
            }
            if (resid) {
                v0 = (E0[c] + v0) * alive0;     v1 = (E0[c + 1] + v1) * alive0;
                v2 = (E1[c] + v2) * alive1;     v3 = (E1[c + 1] + v3) * alive1;
            }
            *(float2*)&Cout[(size_t)r0 * N + c] = make_float2(v0, v1);
            *(float2*)&Cout[(size_t)r1 * N + c] = make_float2(v2, v3);
        }
    }
}

// ---------------- persistent GRU scan ------------------------------------------
#define RPB 4
#define GTH 384
#define WHS_STRIDE 132
#define GRU_SMEM ((384 * WHS_STRIDE + RPB * D + RPB * 384 + D) * 4)

__global__ __launch_bounds__(GTH) void gru_kernel(
    const float* __restrict__ gi,
    const unsigned char* __restrict__ dones,
    const float* __restrict__ h0,
    const float* __restrict__ Wh,
    const float* __restrict__ bhn,
    float* __restrict__ e_out,
    float* __restrict__ hidden_out)
{
    extern __shared__ float sm[];
    float* Whs  = sm;
    float* hs   = Whs + 384 * WHS_STRIDE;
    float* ghs  = hs + RPB * D;
    float* sbhn = ghs + RPB * 384;

    const int tid = threadIdx.x;
    const int rowbase = blockIdx.x * RPB;

    for (int k = 0; k < D; k++)
        Whs[tid * WHS_STRIDE + k] = Wh[(size_t)k * (3 * D) + tid];
    if (tid < D) sbhn[tid] = bhn[tid];
    for (int idx = tid; idx < RPB * D; idx += GTH)
        hs[idx] = h0[(size_t)(rowbase + (idx >> 7)) * D + (idx & 127)];
    __syncthreads();

    for (int t = 0; t < T_STEPS; t++) {
        for (int idx = tid; idx < RPB * D; idx += GTH) {
            const int r = idx >> 7;
            if (dones[t * BATCH + rowbase + r]) hs[idx] = 0.f;
        }
        __syncthreads();

        {
            float a0 = 0.f, a1 = 0.f, a2 = 0.f, a3 = 0.f;
            const float* wp = Whs + tid * WHS_STRIDE;
#pragma unroll 8
            for (int k = 0; k < D; k += 4) {
                const float4 w4 = *(const float4*)(wp + k);
                float4 hv;
                hv = *(const float4*)(hs + 0 * D + k);
                a0 += w4.x * hv.x + w4.y * hv.y + w4.z * hv.z + w4.w * hv.w;
                hv = *(const float4*)(hs + 1 * D + k);
                a1 += w4.x * hv.x + w4.y * hv.y + w4.z * hv.z + w4.w * hv.w;
                hv = *(const float4*)(hs + 2 * D + k);
                a2 += w4.x * hv.x + w4.y * hv.y + w4.z * hv.z + w4.w * hv.w;
                hv = *(const float4*)(hs + 3 * D + k);
                a3 += w4.x * hv.x + w4.y * hv.y + w4.z * hv.z + w4.w * hv.w;
            }
            ghs[0 * 384 + tid] = a0;
            ghs[1 * 384 + tid] = a1;
            ghs[2 * 384 + tid] = a2;
            ghs[3 * 384 + tid] = a3;
        }
        __syncthreads();

        for (int idx = tid; idx < RPB * D; idx += GTH) {
            const int r = idx >> 7, d = idx & 127;
            const int row = rowbase + r;
            const size_t gib = ((size_t)t * BATCH + row) * (3 * D);
            const float i_r = gi[gib + d];
            const float i_z = gi[gib + D + d];
            const float i_n = gi[gib + 2 * D + d];
            const float h_r = ghs[r * 384 + d];
            const float h_z = ghs[r * 384 + D + d];
            const float h_n = ghs[r * 384 + 2 * D + d];
            const float hprev = hs[idx];
            const float rg = 1.f / (1.f + expf(-(i_r + h_r)));
            const float zg = 1.f / (1.f + expf(-(i_z + h_z)));
            const float ng = tanhf(i_n + rg * (h_n + sbhn[d]));
            const float hn = (1.f - zg) * ng + zg * hprev;
            hs[idx] = hn;
            const float alive = dones[t * BATCH + row] ? 0.f : 1.f;
            e_out[((size_t)t * BATCH + row) * D + d] = hn * alive;
        }
    }
    __syncthreads();
    for (int idx = tid; idx < RPB * D; idx += GTH)
        hidden_out[(size_t)(rowbase + (idx >> 7)) * D + (idx & 127)] = hs[idx];
}

// ---------------- fused pairwise-coupling C + context ---------------------------
// reads merged aiaj (row stride 256: [ai | aj])
__global__ __launch_bounds__(256) void couple_ctx_kernel(
    const float* __restrict__ e, const float* __restrict__ aiaj,
    const float* __restrict__ chb,
    const float* __restrict__ cow, const float* __restrict__ cob,
    const unsigned char* __restrict__ dones, float* __restrict__ ctx)
{
    __shared__ float sai[NA * CH], saj[NA * CH], se[NA * D];
    __shared__ float sb[CH], sw[CH];
    __shared__ float sC[NA * NA];
    __shared__ float salive[NA];

    const int g  = blockIdx.x;        // t*NE + group
    const int t  = g >> 6;
    const int eg = g & 63;
    const size_t base  = (size_t)g * NA * D;
    const size_t base2 = (size_t)g * NA * 256;
    const int tid = threadIdx.x;

#pragma unroll
    for (int q = 0; q < 2; q++) {
        const int idx = (tid + q * 256) * 4;
        const int row = idx >> 8;
        const int col = idx & 255;
        const float4 v = *(const float4*)&aiaj[base2 + idx];
        if (col < 128) *(float4*)&sai[row * 128 + col] = v;
        else           *(float4*)&saj[row * 128 + col - 128] = v;
    }
    *(float4*)&se[tid * 4] = *(const float4*)&e[base + tid * 4];
    if (tid < CH) { sb[tid] = chb[tid]; sw[tid] = cow[tid]; }
    if (tid < NA) salive[tid] = dones[t * BATCH + eg * NA + tid] ? 0.f : 1.f;
    __syncthreads();

    const int warp = tid >> 5, lane = tid & 31;
    {
        const int i = warp;
        const float cb = cob[0];
        for (int j = 0; j < NA; j++) {
            float s = 0.f;
#pragma unroll
            for (int k = lane; k < CH; k += 32) {
                const float v = sai[i * CH + k] + saj[j * CH + k] + sb[k];
                s += fmaxf(v, 0.f) * sw[k];
            }
#pragma unroll
            for (int off = 16; off; off >>= 1) s += __shfl_xor_sync(0xffffffffu, s, off);
            if (lane == 0) {
                const float cv = 1.f / (1.f + expf(-(s + cb)));
                sC[i * NA + j] = (i == j) ? 0.f : cv * salive[j];
            }
        }
    }
    __syncthreads();

    for (int idx = tid; idx < NA * D; idx += 256) {
        const int i = idx >> 7, d = idx & 127;
        float s = 0.f;
#pragma unroll
        for (int j = 0; j < NA; j++) s += sC[i * NA + j] * se[j * D + d];
        ctx[base + idx] = s;
    }
}

// ---------------- final value projection (VH -> 1) ------------------------------
__global__ __launch_bounds__(256) void vout_kernel(
    const float* __restrict__ v2, const float* __restrict__ w,
    const float* __restrict__ b, float* __restrict__ out)
{
    __shared__ float sw[VH];
    const int tid = threadIdx.x;
    sw[tid] = w[tid];
    __syncthreads();
    const int warp = tid >> 5, lane = tid & 31;
    const int row = blockIdx.x * 8 + warp;
    const float* vp = v2 + (size_t)row * VH;
    float s = 0.f;
#pragma unroll
    for (int k = lane; k < VH; k += 32) s += vp[k] * sw[k];
#pragma unroll
    for (int off = 16; off; off >>= 1) s += __shfl_xor_sync(0xffffffffu, s, off);
    if (lane == 0) out[row] = s + b[0];
}

// ---------------- launcher -------------------------------------------------------
extern "C" void kernel_launch(void* const* d_in, const int* in_sizes, int n_in,
                              void* d_out, int out_size)
{
    const float* hidden = (const float*)d_in[0];
    const float* obs    = (const float*)d_in[1];
    const void*  dones_raw = d_in[2];
    const float* e1w = (const float*)d_in[3];
    const float* e1b = (const float*)d_in[4];
    const float* e2w = (const float*)d_in[5];
    const float* e2b = (const float*)d_in[6];
    const float* gWi = (const float*)d_in[7];
    const float* gbi = (const float*)d_in[8];
    const float* gWh = (const float*)d_in[9];
    const float* gbhn = (const float*)d_in[10];
    const float* chw = (const float*)d_in[11];
    const float* chb = (const float*)d_in[12];
    const float* cow = (const float*)d_in[13];
    const float* cob = (const float*)d_in[14];
    const float* uhw = (const float*)d_in[15];
    const float* uhb = (const float*)d_in[16];
    const float* uow = (const float*)d_in[17];
    const float* uob = (const float*)d_in[18];
    const float* v1w = (const float*)d_in[19];
    const float* v1b = (const float*)d_in[20];
    const float* v2w = (const float*)d_in[21];
    const float* v2b = (const float*)d_in[22];
    const float* vow = (const float*)d_in[23];
    const float* vob = (const float*)d_in[24];

    float* out_hidden = (float*)d_out;                 // (B, D)
    float* out_values = (float*)d_out + BATCH * D;     // (T, B)

    float *emb1, *emb2, *gi, *e, *aiaj, *ctx, *d1, *v1, *v2;
    unsigned char* dmask;
    cudaGetSymbolAddress((void**)&emb1, g_emb1);
    cudaGetSymbolAddress((void**)&emb2, g_emb2);
    cudaGetSymbolAddress((void**)&gi,   g_gi);
    cudaGetSymbolAddress((void**)&e,    g_e);
    cudaGetSymbolAddress((void**)&aiaj, g_aiaj);
    cudaGetSymbolAddress((void**)&ctx,  g_ctx);
    cudaGetSymbolAddress((void**)&d1,   g_d1);
    cudaGetSymbolAddress((void**)&v1,   g_v1);
    cudaGetSymbolAddress((void**)&v2,   g_v2);
    cudaGetSymbolAddress((void**)&dmask, g_dmask);

    cudaFuncSetAttribute(gru_kernel, cudaFuncAttributeMaxDynamicSharedMemorySize, GRU_SMEM);

    const int M = TB;
    const dim3 blk(256);

    detect_dones_kernel<<<1, 256>>>((const unsigned char*)dones_raw, TB);
    conv_dones_kernel<<<TB / 256, 256>>>(dones_raw, TB);

    // embed1: relu(obs @ e1w + e1b)
    tgemm_kernel<<<dim3(D / BN, M / BM), blk>>>(M, D, OBS, D, obs, e1w,
        nullptr, nullptr, e1b, emb1, 1, nullptr, nullptr);
    // embed2: relu(emb1 @ e2w + e2b)
    tgemm_kernel<<<dim3(D / BN, M / BM), blk>>>(M, D, D, D, emb1, e2w,
        nullptr, nullptr, e2b, emb2, 1, nullptr, nullptr);
    // gi = emb2 @ gWi + gbi
    tgemm_kernel<<<dim3(3 * D / BN, M / BM), blk>>>(M, 3 * D, D, 3 * D, emb2, gWi,
        nullptr, nullptr, gbi, gi, 0, nullptr, nullptr);
    // sequential GRU scan
    gru_kernel<<<BATCH / RPB, GTH, GRU_SMEM>>>(gi, dmask, hidden, gWh, gbhn, e, out_hidden);

    for (int it = 0; it < ITERS; it++) {
        // [ai | aj] = e @ [W1 | W2]  (one N=256 GEMM, column-split B)
        tgemm_kernel<<<dim3(2 * CH / BN, M / BM), blk>>>(M, 2 * CH, D, CH, e, chw,
            nullptr, chw + (size_t)D * CH, nullptr, aiaj, 8, nullptr, nullptr);
        couple_ctx_kernel<<<T_STEPS * NE, 256>>>(e, aiaj, chb, cow, cob, dmask, ctx);
        // d1 = relu(e @ U1 + ctx @ U2 + uhb)
        tgemm_kernel<<<dim3(D / BN, M / BM), blk>>>(M, D, D, D, e, uhw,
            ctx, uhw + (size_t)D * D, uhb, d1, 1 | 2, nullptr, nullptr);
        // e = (e + relu(d1 @ uow + uob)) * alive   (in place)
        tgemm_kernel<<<dim3(D / BN, M / BM), blk>>>(M, D, D, D, d1, uow,
            nullptr, nullptr, uob, e, 4, e, dmask);
    }

    // value head
    tgemm_kernel<<<dim3(VH / BN, M / BM), blk>>>(M, VH, D, VH, e, v1w,
        nullptr, nullptr, v1b, v1, 1, nullptr, nullptr);
    tgemm_kernel<<<dim3(VH / BN, M / BM), blk>>>(M, VH, VH, VH, v1, v2w,
        nullptr, nullptr, v2b, v2, 1, nullptr, nullptr);
    vout_kernel<<<TB / 8, 256>>>(v2, vow, vob, out_values);
}

// round 7
// speedup vs baseline: 1.1167x; 1.1167x over previous
#include <cuda_runtime.h>
#include <cuda_bf16.h>
#include <math.h>

#define T_STEPS 128
#define NE 64
#define NA 8
#define OBS 64
#define D 128
#define CH 128
#define VH 256
#define BATCH 512           // NE*NA
#define TB (T_STEPS*BATCH)  // 65536
#define ITERS 2

// ---------------- scratch (static device arrays: allocation-free) -------------
__device__ float g_emb1[TB * D];
__device__ float g_emb2[TB * D];
__device__ float g_gi[TB * 3 * D];
__device__ float g_e[TB * D];
__device__ float g_aiaj[TB * 2 * CH];   // merged [ai | aj], row stride 256
__device__ float g_ctx[TB * D];
__device__ float g_d1[TB * D];
__device__ float g_v1[TB * VH];
__device__ float g_v2[TB * VH];
__device__ unsigned char g_dmask[TB];
__device__ int g_dflag;   // 0 = uint8/bool, 1 = float32, 2 = int32

// ---------------- dones dtype detection + canonicalization --------------------
__global__ void detect_dones_kernel(const unsigned char* __restrict__ p, int n)
{
    __shared__ int s_nonbin, s_off4;
    if (threadIdx.x == 0) { s_nonbin = 0; s_off4 = 0; }
    __syncthreads();
    int nb = 0, o4 = 0;
    for (int i = threadIdx.x; i < n; i += blockDim.x) {
        const unsigned char b = p[i];
        if (b > 1) nb = 1;
        else if (b == 1 && (i & 3)) o4 = 1;
    }
    if (nb) atomicOr(&s_nonbin, 1);
    if (o4) atomicOr(&s_off4, 1);
    __syncthreads();
    if (threadIdx.x == 0)
        g_dflag = s_nonbin ? 1 : (s_off4 ? 0 : 2);
}

__global__ void conv_dones_kernel(const void* __restrict__ p, int n)
{
    const int i = blockIdx.x * blockDim.x + threadIdx.x;
    if (i >= n) return;
    const int f = g_dflag;
    unsigned char m;
    if (f == 1)      m = (((const float*)p)[i] != 0.f);
    else if (f == 2) m = (((const int*)p)[i] != 0);
    else             m = (((const unsigned char*)p)[i] != 0);
    g_dmask[i] = m;
}

// ---------------- BF16 tensor-core GEMM (2-way split, 3 products ~ fp32) -------
// C[M,N] = epilogue( A[M,K] @ B[K,N] (+ A2 @ B2) + bias )
// flags: 1 relu | 2 dual-source | 4 resid+alive | 8 B column-split
#define BM 128
#define BN 128
#define BK 16
#define AST 12      // As row stride in u32
#define BST 136     // Bs row stride in u32

__device__ __forceinline__ unsigned pack_bf16(float lo_elem, float hi_elem)
{
    unsigned d;
    asm("cvt.rn.bf16x2.f32 %0, %1, %2;" : "=r"(d) : "f"(hi_elem), "f"(lo_elem));
    return d;
}

__device__ __forceinline__ void mma_bf16(float* c, const unsigned* a, const unsigned* b)
{
    asm volatile(
        "mma.sync.aligned.m16n8k16.row.col.f32.bf16.bf16.f32 "
        "{%0,%1,%2,%3}, {%4,%5,%6,%7}, {%8,%9}, {%0,%1,%2,%3};"
        : "+f"(c[0]), "+f"(c[1]), "+f"(c[2]), "+f"(c[3])
        : "r"(a[0]), "r"(a[1]), "r"(a[2]), "r"(a[3]), "r"(b[0]), "r"(b[1]));
}

__global__ __launch_bounds__(256) void tgemm_kernel(
    int M, int N, int K, int ldb,
    const float* __restrict__ A, const float* __restrict__ Bm,
    const float* __restrict__ A2, const float* __restrict__ B2,
    const float* __restrict__ bias, float* __restrict__ Cout,
    int flags, const float* __restrict__ Ein,
    const unsigned char* __restrict__ dones)
{
    __shared__ __align__(16) unsigned As[2][2][BM * AST];
    __shared__ __align__(16) unsigned Bs[2][2][(BK / 2) * BST];

    const int tid  = threadIdx.x;
    const int brow = blockIdx.y * BM;
    const int bcol = blockIdx.x * BN;
    const int w    = tid >> 5, lane = tid & 31;
    const int gid  = lane >> 2, tig = lane & 3;
    const int wm   = (w & 1) * 64;
    const int wn   = (w >> 1) * 32;

    const int arow0 = tid >> 2;
    const int afc   = (tid & 3) * 4;
    const int brw   = tid >> 5;
    const int bfc   = (tid & 31) * 4;

    float acc[4][4][4];
#pragma unroll
    for (int i = 0; i < 4; i++)
#pragma unroll
        for (int j = 0; j < 4; j++)
#pragma unroll
            for (int q = 0; q < 4; q++) acc[i][j][q] = 0.f;

    const int nsrc = (flags & 2) ? 2 : 1;
    const int tilesPerSrc = K / BK;
    const int ntiles = nsrc * tilesPerSrc;

    float4 rA[2], rB[2];

    auto loadTile = [&](int t) {
        const int s  = (t >= tilesPerSrc) ? 1 : 0;
        const int k0 = (t - s * tilesPerSrc) * BK;
        const float* Ap = s ? A2 : A;
        const float* Bp;
        int bc;
        if (flags & 8) { Bp = (bcol >= BN) ? B2 : Bm; bc = 0; }
        else           { Bp = s ? B2 : Bm;            bc = bcol; }
        rA[0] = *(const float4*)(Ap + (size_t)(brow + arow0) * K + k0 + afc);
        rA[1] = *(const float4*)(Ap + (size_t)(brow + arow0 + 64) * K + k0 + afc);
        rB[0] = *(const float4*)(Bp + (size_t)(k0 + 2 * brw) * ldb + bc + bfc);
        rB[1] = *(const float4*)(Bp + (size_t)(k0 + 2 * brw + 1) * ldb + bc + bfc);
    };

    auto storeTile = [&](int buf) {
#pragma unroll
        for (int p = 0; p < 2; p++) {
            const float4 v = rA[p];
            const float h0 = __bfloat162float(__float2bfloat16(v.x));
            const float h1 = __bfloat162float(__float2bfloat16(v.y));
            const float h2 = __bfloat162float(__float2bfloat16(v.z));
            const float h3 = __bfloat162float(__float2bfloat16(v.w));
            const int base = (arow0 + p * 64) * AST + (tid & 3) * 2;
            *(uint2*)&As[buf][0][base] = make_uint2(pack_bf16(h0, h1), pack_bf16(h2, h3));
            *(uint2*)&As[buf][1][base] = make_uint2(pack_bf16(v.x - h0, v.y - h1),
                                                    pack_bf16(v.z - h2, v.w - h3));
        }
        {
            const float4 va = rB[0], vb = rB[1];
            float ha0 = __bfloat162float(__float2bfloat16(va.x));
            float ha1 = __bfloat162float(__float2bfloat16(va.y));
            float ha2 = __bfloat162float(__float2bfloat16(va.z));
            float ha3 = __bfloat162float(__float2bfloat16(va.w));
            float hb0 = __bfloat162float(__float2bfloat16(vb.x));
            float hb1 = __bfloat162float(__float2bfloat16(vb.y));
            float hb2 = __bfloat162float(__float2bfloat16(vb.z));
            float hb3 = __bfloat162float(__float2bfloat16(vb.w));
            const int base = brw * BST + bfc;
            *(uint4*)&Bs[buf][0][base] = make_uint4(
                pack_bf16(ha0, hb0), pack_bf16(ha1, hb1),
                pack_bf16(ha2, hb2), pack_bf16(ha3, hb3));
            *(uint4*)&Bs[buf][1][base] = make_uint4(
                pack_bf16(va.x - ha0, vb.x - hb0), pack_bf16(va.y - ha1, vb.y - hb1),
                pack_bf16(va.z - ha2, vb.z - hb2), pack_bf16(va.w - ha3, vb.w - hb3));
        }
    };

    loadTile(0);
    storeTile(0);
    __syncthreads();

    for (int t = 0; t < ntiles; t++) {
        if (t + 1 < ntiles) loadTile(t + 1);

        const unsigned* Ash = As[t & 1][0];
        const unsigned* Asl = As[t & 1][1];
        const unsigned* Bsh = Bs[t & 1][0];
        const unsigned* Bsl = Bs[t & 1][1];

        unsigned bh[4][2], bl[4][2];
#pragma unroll
        for (int ns = 0; ns < 4; ns++) {
            const int n = wn + ns * 8 + gid;
            bh[ns][0] = Bsh[tig * BST + n];
            bh[ns][1] = Bsh[(tig + 4) * BST + n];
            bl[ns][0] = Bsl[tig * BST + n];
            bl[ns][1] = Bsl[(tig + 4) * BST + n];
        }
#pragma unroll
        for (int ms = 0; ms < 4; ms++) {
            const int m0 = wm + ms * 16 + gid;
            unsigned ah[4], al[4];
            ah[0] = Ash[m0 * AST + tig];
            ah[1] = Ash[(m0 + 8) * AST + tig];
            ah[2] = Ash[m0 * AST + tig + 4];
            ah[3] = Ash[(m0 + 8) * AST + tig + 4];
            al[0] = Asl[m0 * AST + tig];
            al[1] = Asl[(m0 + 8) * AST + tig];
            al[2] = Asl[m0 * AST + tig + 4];
            al[3] = Asl[(m0 + 8) * AST + tig + 4];
#pragma unroll
            for (int ns = 0; ns < 4; ns++) {
                mma_bf16(acc[ms][ns], ah, bh[ns]);
                mma_bf16(acc[ms][ns], ah, bl[ns]);
                mma_bf16(acc[ms][ns], al, bh[ns]);
            }
        }

        if (t + 1 < ntiles) {
            storeTile((t + 1) & 1);
            __syncthreads();
        }
    }

    const bool hasb   = (bias != nullptr);
    const bool resid  = (flags & 4);
    const bool dorelu = (flags & 5);
#pragma unroll
    for (int ms = 0; ms < 4; ms++) {
        const int r0 = brow + wm + ms * 16 + gid;
        const int r1 = r0 + 8;
        float alive0 = 1.f, alive1 = 1.f;
        const float *E0 = nullptr, *E1 = nullptr;
        if (resid) {
            alive0 = dones[r0] ? 0.f : 1.f;
            alive1 = dones[r1] ? 0.f : 1.f;
            E0 = Ein + (size_t)r0 * N;
            E1 = Ein + (size_t)r1 * N;
        }
#pragma unroll
        for (int ns = 0; ns < 4; ns++) {
            const int c = bcol + wn + ns * 8 + tig * 2;
            float b0 = 0.f, b1 = 0.f;
            if (hasb) { b0 = bias[c]; b1 = bias[c + 1]; }
            float v0 = acc[ms][ns][0] + b0;
            float v1 = acc[ms][ns][1] + b1;
            float v2 = acc[ms][ns][2] + b0;
            float v3 = acc[ms][ns][3] + b1;
            if (dorelu) {
                v0 = fmaxf(v0, 0.f); v1 = fmaxf(v1, 0.f);
                v2 = fmaxf(v2, 0.f); v3 = fmaxf(v3, 0.f);
            }
            if (resid) {
                v0 = (E0[c] + v0) * alive0;     v1 = (E0[c + 1] + v1) * alive0;
                v2 = (E1[c] + v2) * alive1;     v3 = (E1[c + 1] + v3) * alive1;
            }
            *(float2*)&Cout[(size_t)r0 * N + c] = make_float2(v0, v1);
            *(float2*)&Cout[(size_t)r1 * N + c] = make_float2(v2, v3);
        }
    }
}

// ---------------- persistent GRU scan v2: Wh in registers, f32x2 FMA -----------
// 128 blocks x 4 rows; 384 threads, thread tid owns Wh column tid (64 f32x2 regs).
// h stored in smem as [kpair][4 rows] float2 -> broadcast LDS.128 loads.
#define RPB 4
#define GTH 384

__device__ __forceinline__ unsigned long long fma_f32x2(
    unsigned long long a, unsigned long long b, unsigned long long c)
{
    unsigned long long d;
    asm("fma.rn.f32x2 %0, %1, %2, %3;" : "=l"(d) : "l"(a), "l"(b), "l"(c));
    return d;
}

__device__ __forceinline__ float sig_fast(float x)
{
    return __fdividef(1.f, 1.f + __expf(-x));
}
__device__ __forceinline__ float tanh_fast(float x)
{
    return __fdividef(2.f, 1.f + __expf(-2.f * x)) - 1.f;
}

__global__ __launch_bounds__(GTH, 1) void gru_kernel(
    const float* __restrict__ gi,            // (T,B,3D) = x@Wi + bi
    const unsigned char* __restrict__ dones, // (T,B) canonical mask
    const float* __restrict__ h0,            // (B,D)
    const float* __restrict__ Wh,            // (D,3D) row-major
    const float* __restrict__ bhn,           // (D)
    float* __restrict__ e_out,               // (T,B,D) = new_h * alive
    float* __restrict__ hidden_out)          // (B,D)
{
    __shared__ __align__(16) float hs2[64 * 8];   // [kpair][r*2 + (lo/hi)] = h[r][2kp+..]
    __shared__ float ghs[RPB * 384];
    __shared__ float sbhn[D];

    const int tid = threadIdx.x;               // column id 0..383
    const int rowbase = blockIdx.x * RPB;

    // Wh column -> 64 f32x2 registers (coalesced loads across threads)
    unsigned long long w[64];
#pragma unroll
    for (int kp = 0; kp < 64; kp++) {
        const unsigned lo = __float_as_uint(Wh[(size_t)(2 * kp) * 384 + tid]);
        const unsigned hi = __float_as_uint(Wh[(size_t)(2 * kp + 1) * 384 + tid]);
        w[kp] = ((unsigned long long)hi << 32) | lo;
    }
    if (tid < D) sbhn[tid] = bhn[tid];

    // init h (apply dones[0] reset)
    for (int idx = tid; idx < RPB * D; idx += GTH) {
        const int r = idx >> 7, d = idx & 127;
        const int row = rowbase + r;
        float v = dones[row] ? 0.f : h0[(size_t)row * D + d];
        hs2[(d >> 1) * 8 + r * 2 + (d & 1)] = v;
    }
    __syncthreads();

    for (int t = 0; t < T_STEPS; t++) {
        // gh[r][tid] = sum_k h[r][k] * Wh[k][tid]   (f32x2 packed over k-pairs)
        {
            unsigned long long a0 = 0, a1 = 0, a2 = 0, a3 = 0;
#pragma unroll
            for (int kp = 0; kp < 64; kp++) {
                const ulonglong2 p01 = *(const ulonglong2*)(hs2 + kp * 8);
                const ulonglong2 p23 = *(const ulonglong2*)(hs2 + kp * 8 + 4);
                a0 = fma_f32x2(w[kp], p01.x, a0);
                a1 = fma_f32x2(w[kp], p01.y, a1);
                a2 = fma_f32x2(w[kp], p23.x, a2);
                a3 = fma_f32x2(w[kp], p23.y, a3);
            }
            ghs[0 * 384 + tid] = __uint_as_float((unsigned)a0) + __uint_as_float((unsigned)(a0 >> 32));
            ghs[1 * 384 + tid] = __uint_as_float((unsigned)a1) + __uint_as_float((unsigned)(a1 >> 32));
            ghs[2 * 384 + tid] = __uint_as_float((unsigned)a2) + __uint_as_float((unsigned)(a2 >> 32));
            ghs[3 * 384 + tid] = __uint_as_float((unsigned)a3) + __uint_as_float((unsigned)(a3 >> 32));
        }
        __syncthreads();

        // gates; store next-h with dones[t+1] reset folded in
        for (int idx = tid; idx < RPB * D; idx += GTH) {
            const int r = idx >> 7, d = idx & 127;
            const int row = rowbase + r;
            const size_t gib = ((size_t)t * BATCH + row) * (3 * D);
            const float i_r = gi[gib + d];
            const float i_z = gi[gib + D + d];
            const float i_n = gi[gib + 2 * D + d];
            const float h_r = ghs[r * 384 + d];
            const float h_z = ghs[r * 384 + D + d];
            const float h_n = ghs[r * 384 + 2 * D + d];
            const int hsidx = (d >> 1) * 8 + r * 2 + (d & 1);
            const float hprev = hs2[hsidx];
            const float rg = sig_fast(i_r + h_r);
            const float zg = sig_fast(i_z + h_z);
            const float ng = tanh_fast(i_n + rg * (h_n + sbhn[d]));
            const float hn = (1.f - zg) * ng + zg * hprev;
            const float alive = dones[t * BATCH + row] ? 0.f : 1.f;
            e_out[((size_t)t * BATCH + row) * D + d] = hn * alive;
            if (t == T_STEPS - 1) {
                hidden_out[(size_t)row * D + d] = hn;
            } else {
                hs2[hsidx] = dones[(t + 1) * BATCH + row] ? 0.f : hn;
            }
        }
        __syncthreads();
    }
}

// ---------------- fused pairwise-coupling C + context ---------------------------
__global__ __launch_bounds__(256) void couple_ctx_kernel(
    const float* __restrict__ e, const float* __restrict__ aiaj,
    const float* __restrict__ chb,
    const float* __restrict__ cow, const float* __restrict__ cob,
    const unsigned char* __restrict__ dones, float* __restrict__ ctx)
{
    __shared__ float sai[NA * CH], saj[NA * CH], se[NA * D];
    __shared__ float sb[CH], sw[CH];
    __shared__ float sC[NA * NA];
    __shared__ float salive[NA];

    const int g  = blockIdx.x;
    const int t  = g >> 6;
    const int eg = g & 63;
    const size_t base  = (size_t)g * NA * D;
    const size_t base2 = (size_t)g * NA * 256;
    const int tid = threadIdx.x;

#pragma unroll
    for (int q = 0; q < 2; q++) {
        const int idx = (tid + q * 256) * 4;
        const int row = idx >> 8;
        const int col = idx & 255;
        const float4 v = *(const float4*)&aiaj[base2 + idx];
        if (col < 128) *(float4*)&sai[row * 128 + col] = v;
        else           *(float4*)&saj[row * 128 + col - 128] = v;
    }
    *(float4*)&se[tid * 4] = *(const float4*)&e[base + tid * 4];
    if (tid < CH) { sb[tid] = chb[tid]; sw[tid] = cow[tid]; }
    if (tid < NA) salive[tid] = dones[t * BATCH + eg * NA + tid] ? 0.f : 1.f;
    __syncthreads();

    const int warp = tid >> 5, lane = tid & 31;
    {
        const int i = warp;
        const float cb = cob[0];
        for (int j = 0; j < NA; j++) {
            float s = 0.f;
#pragma unroll
            for (int k = lane; k < CH; k += 32) {
                const float v = sai[i * CH + k] + saj[j * CH + k] + sb[k];
                s += fmaxf(v, 0.f) * sw[k];
            }
#pragma unroll
            for (int off = 16; off; off >>= 1) s += __shfl_xor_sync(0xffffffffu, s, off);
            if (lane == 0) {
                const float cv = 1.f / (1.f + expf(-(s + cb)));
                sC[i * NA + j] = (i == j) ? 0.f : cv * salive[j];
            }
        }
    }
    __syncthreads();

    for (int idx = tid; idx < NA * D; idx += 256) {
        const int i = idx >> 7, d = idx & 127;
        float s = 0.f;
#pragma unroll
        for (int j = 0; j < NA; j++) s += sC[i * NA + j] * se[j * D + d];
        ctx[base + idx] = s;
    }
}

// ---------------- final value projection (VH -> 1) ------------------------------
__global__ __launch_bounds__(256) void vout_kernel(
    const float* __restrict__ v2, const float* __restrict__ w,
    const float* __restrict__ b, float* __restrict__ out)
{
    __shared__ float sw[VH];
    const int tid = threadIdx.x;
    sw[tid] = w[tid];
    __syncthreads();
    const int warp = tid >> 5, lane = tid & 31;
    const int row = blockIdx.x * 8 + warp;
    const float* vp = v2 + (size_t)row * VH;
    float s = 0.f;
#pragma unroll
    for (int k = lane; k < VH; k += 32) s += vp[k] * sw[k];
#pragma unroll
    for (int off = 16; off; off >>= 1) s += __shfl_xor_sync(0xffffffffu, s, off);
    if (lane == 0) out[row] = s + b[0];
}

// ---------------- launcher -------------------------------------------------------
extern "C" void kernel_launch(void* const* d_in, const int* in_sizes, int n_in,
                              void* d_out, int out_size)
{
    const float* hidden = (const float*)d_in[0];
    const float* obs    = (const float*)d_in[1];
    const void*  dones_raw = d_in[2];
    const float* e1w = (const float*)d_in[3];
    const float* e1b = (const float*)d_in[4];
    const float* e2w = (const float*)d_in[5];
    const float* e2b = (const float*)d_in[6];
    const float* gWi = (const float*)d_in[7];
    const float* gbi = (const float*)d_in[8];
    const float* gWh = (const float*)d_in[9];
    const float* gbhn = (const float*)d_in[10];
    const float* chw = (const float*)d_in[11];
    const float* chb = (const float*)d_in[12];
    const float* cow = (const float*)d_in[13];
    const float* cob = (const float*)d_in[14];
    const float* uhw = (const float*)d_in[15];
    const float* uhb = (const float*)d_in[16];
    const float* uow = (const float*)d_in[17];
    const float* uob = (const float*)d_in[18];
    const float* v1w = (const float*)d_in[19];
    const float* v1b = (const float*)d_in[20];
    const float* v2w = (const float*)d_in[21];
    const float* v2b = (const float*)d_in[22];
    const float* vow = (const float*)d_in[23];
    const float* vob = (const float*)d_in[24];

    float* out_hidden = (float*)d_out;                 // (B, D)
    float* out_values = (float*)d_out + BATCH * D;     // (T, B)

    float *emb1, *emb2, *gi, *e, *aiaj, *ctx, *d1, *v1, *v2;
    unsigned char* dmask;
    cudaGetSymbolAddress((void**)&emb1, g_emb1);
    cudaGetSymbolAddress((void**)&emb2, g_emb2);
    cudaGetSymbolAddress((void**)&gi,   g_gi);
    cudaGetSymbolAddress((void**)&e,    g_e);
    cudaGetSymbolAddress((void**)&aiaj, g_aiaj);
    cudaGetSymbolAddress((void**)&ctx,  g_ctx);
    cudaGetSymbolAddress((void**)&d1,   g_d1);
    cudaGetSymbolAddress((void**)&v1,   g_v1);
    cudaGetSymbolAddress((void**)&v2,   g_v2);
    cudaGetSymbolAddress((void**)&dmask, g_dmask);

    const int M = TB;
    const dim3 blk(256);

    detect_dones_kernel<<<1, 256>>>((const unsigned char*)dones_raw, TB);
    conv_dones_kernel<<<TB / 256, 256>>>(dones_raw, TB);

    // embed1: relu(obs @ e1w + e1b)
    tgemm_kernel<<<dim3(D / BN, M / BM), blk>>>(M, D, OBS, D, obs, e1w,
        nullptr, nullptr, e1b, emb1, 1, nullptr, nullptr);
    // embed2: relu(emb1 @ e2w + e2b)
    tgemm_kernel<<<dim3(D / BN, M / BM), blk>>>(M, D, D, D, emb1, e2w,
        nullptr, nullptr, e2b, emb2, 1, nullptr, nullptr);
    // gi = emb2 @ gWi + gbi
    tgemm_kernel<<<dim3(3 * D / BN, M / BM), blk>>>(M, 3 * D, D, 3 * D, emb2, gWi,
        nullptr, nullptr, gbi, gi, 0, nullptr, nullptr);
    // sequential GRU scan (register-resident Wh, f32x2 FMA)
    gru_kernel<<<BATCH / RPB, GTH>>>(gi, dmask, hidden, gWh, gbhn, e, out_hidden);

    for (int it = 0; it < ITERS; it++) {
        // [ai | aj] = e @ [W1 | W2]
        tgemm_kernel<<<dim3(2 * CH / BN, M / BM), blk>>>(M, 2 * CH, D, CH, e, chw,
            nullptr, chw + (size_t)D * CH, nullptr, aiaj, 8, nullptr, nullptr);
        couple_ctx_kernel<<<T_STEPS * NE, 256>>>(e, aiaj, chb, cow, cob, dmask, ctx);
        // d1 = relu(e @ U1 + ctx @ U2 + uhb)
        tgemm_kernel<<<dim3(D / BN, M / BM), blk>>>(M, D, D, D, e, uhw,
            ctx, uhw + (size_t)D * D, uhb, d1, 1 | 2, nullptr, nullptr);
        // e = (e + relu(d1 @ uow + uob)) * alive   (in place)
        tgemm_kernel<<<dim3(D / BN, M / BM), blk>>>(M, D, D, D, d1, uow,
            nullptr, nullptr, uob, e, 4, e, dmask);
    }

    // value head
    tgemm_kernel<<<dim3(VH / BN, M / BM), blk>>>(M, VH, D, VH, e, v1w,
        nullptr, nullptr, v1b, v1, 1, nullptr, nullptr);
    tgemm_kernel<<<dim3(VH / BN, M / BM), blk>>>(M, VH, VH, VH, v1, v2w,
        nullptr, nullptr, v2b, v2, 1, nullptr, nullptr);
    vout_kernel<<<TB / 8, 256>>>(v2, vow, vob, out_values);
}

// round 8
// speedup vs baseline: 1.1214x; 1.0042x over previous
#include <cuda_runtime.h>
#include <cuda_bf16.h>
#include <math.h>

#define T_STEPS 128
#define NE 64
#define NA 8
#define OBS 64
#define D 128
#define CH 128
#define VH 256
#define BATCH 512           // NE*NA
#define TB (T_STEPS*BATCH)  // 65536
#define ITERS 2

// ---------------- scratch (static device arrays: allocation-free) -------------
__device__ float g_emb1[TB * D];
__device__ float g_emb2[TB * D];
__device__ float g_gi[TB * 3 * D];
__device__ float g_e[TB * D];
__device__ float g_aiaj[TB * 2 * CH];   // merged [ai | aj], row stride 256
__device__ float g_ctx[TB * D];
__device__ float g_d1[TB * D];
__device__ float g_v1[TB * VH];
__device__ float g_v2[TB * VH];
__device__ unsigned char g_dmask[TB];
__device__ int g_dflag;   // 0 = uint8/bool, 1 = float32, 2 = int32

// ---------------- dones dtype detection + canonicalization --------------------
__global__ void detect_dones_kernel(const unsigned char* __restrict__ p, int n)
{
    __shared__ int s_nonbin, s_off4;
    if (threadIdx.x == 0) { s_nonbin = 0; s_off4 = 0; }
    __syncthreads();
    int nb = 0, o4 = 0;
    for (int i = threadIdx.x; i < n; i += blockDim.x) {
        const unsigned char b = p[i];
        if (b > 1) nb = 1;
        else if (b == 1 && (i & 3)) o4 = 1;
    }
    if (nb) atomicOr(&s_nonbin, 1);
    if (o4) atomicOr(&s_off4, 1);
    __syncthreads();
    if (threadIdx.x == 0)
        g_dflag = s_nonbin ? 1 : (s_off4 ? 0 : 2);
}

__global__ void conv_dones_kernel(const void* __restrict__ p, int n)
{
    const int i = blockIdx.x * blockDim.x + threadIdx.x;
    if (i >= n) return;
    const int f = g_dflag;
    unsigned char m;
    if (f == 1)      m = (((const float*)p)[i] != 0.f);
    else if (f == 2) m = (((const int*)p)[i] != 0);
    else             m = (((const unsigned char*)p)[i] != 0);
    g_dmask[i] = m;
}

// ---------------- BF16 tensor-core GEMM (2-way split, 3 products ~ fp32) -------
// C[M,N] = epilogue( A[M,K] @ B[K,N] (+ A2 @ B2) + bias )
// flags: 1 relu | 2 dual-source | 4 resid+alive | 8 B column-split
#define BM 128
#define BN 128
#define BK 16
#define AST 12      // As row stride in u32
#define BST 136     // Bs row stride in u32

__device__ __forceinline__ unsigned pack_bf16(float lo_elem, float hi_elem)
{
    unsigned d;
    asm("cvt.rn.bf16x2.f32 %0, %1, %2;" : "=r"(d) : "f"(hi_elem), "f"(lo_elem));
    return d;
}

__device__ __forceinline__ void mma_bf16(float* c, const unsigned* a, const unsigned* b)
{
    asm volatile(
        "mma.sync.aligned.m16n8k16.row.col.f32.bf16.bf16.f32 "
        "{%0,%1,%2,%3}, {%4,%5,%6,%7}, {%8,%9}, {%0,%1,%2,%3};"
        : "+f"(c[0]), "+f"(c[1]), "+f"(c[2]), "+f"(c[3])
        : "r"(a[0]), "r"(a[1]), "r"(a[2]), "r"(a[3]), "r"(b[0]), "r"(b[1]));
}

__global__ __launch_bounds__(256) void tgemm_kernel(
    int M, int N, int K, int ldb,
    const float* __restrict__ A, const float* __restrict__ Bm,
    const float* __restrict__ A2, const float* __restrict__ B2,
    const float* __restrict__ bias, float* __restrict__ Cout,
    int flags, const float* __restrict__ Ein,
    const unsigned char* __restrict__ dones)
{
    __shared__ __align__(16) unsigned As[2][2][BM * AST];
    __shared__ __align__(16) unsigned Bs[2][2][(BK / 2) * BST];

    const int tid  = threadIdx.x;
    const int brow = blockIdx.y * BM;
    const int bcol = blockIdx.x * BN;
    const int w    = tid >> 5, lane = tid & 31;
    const int gid  = lane >> 2, tig = lane & 3;
    const int wm   = (w & 1) * 64;
    const int wn   = (w >> 1) * 32;

    const int arow0 = tid >> 2;
    const int afc   = (tid & 3) * 4;
    const int brw   = tid >> 5;
    const int bfc   = (tid & 31) * 4;

    float acc[4][4][4];
#pragma unroll
    for (int i = 0; i < 4; i++)
#pragma unroll
        for (int j = 0; j < 4; j++)
#pragma unroll
            for (int q = 0; q < 4; q++) acc[i][j][q] = 0.f;

    const int nsrc = (flags & 2) ? 2 : 1;
    const int tilesPerSrc = K / BK;
    const int ntiles = nsrc * tilesPerSrc;

    float4 rA[2], rB[2];

    auto loadTile = [&](int t) {
        const int s  = (t >= tilesPerSrc) ? 1 : 0;
        const int k0 = (t - s * tilesPerSrc) * BK;
        const float* Ap = s ? A2 : A;
        const float* Bp;
        int bc;
        if (flags & 8) { Bp = (bcol >= BN) ? B2 : Bm; bc = 0; }
        else           { Bp = s ? B2 : Bm;            bc = bcol; }
        rA[0] = *(const float4*)(Ap + (size_t)(brow + arow0) * K + k0 + afc);
        rA[1] = *(const float4*)(Ap + (size_t)(brow + arow0 + 64) * K + k0 + afc);
        rB[0] = *(const float4*)(Bp + (size_t)(k0 + 2 * brw) * ldb + bc + bfc);
        rB[1] = *(const float4*)(Bp + (size_t)(k0 + 2 * brw + 1) * ldb + bc + bfc);
    };

    auto storeTile = [&](int buf) {
#pragma unroll
        for (int p = 0; p < 2; p++) {
            const float4 v = rA[p];
            const float h0 = __bfloat162float(__float2bfloat16(v.x));
            const float h1 = __bfloat162float(__float2bfloat16(v.y));
            const float h2 = __bfloat162float(__float2bfloat16(v.z));
            const float h3 = __bfloat162float(__float2bfloat16(v.w));
            const int base = (arow0 + p * 64) * AST + (tid & 3) * 2;
            *(uint2*)&As[buf][0][base] = make_uint2(pack_bf16(h0, h1), pack_bf16(h2, h3));
            *(uint2*)&As[buf][1][base] = make_uint2(pack_bf16(v.x - h0, v.y - h1),
                                                    pack_bf16(v.z - h2, v.w - h3));
        }
        {
            const float4 va = rB[0], vb = rB[1];
            float ha0 = __bfloat162float(__float2bfloat16(va.x));
            float ha1 = __bfloat162float(__float2bfloat16(va.y));
            float ha2 = __bfloat162float(__float2bfloat16(va.z));
            float ha3 = __bfloat162float(__float2bfloat16(va.w));
            float hb0 = __bfloat162float(__float2bfloat16(vb.x));
            float hb1 = __bfloat162float(__float2bfloat16(vb.y));
            float hb2 = __bfloat162float(__float2bfloat16(vb.z));
            float hb3 = __bfloat162float(__float2bfloat16(vb.w));
            const int base = brw * BST + bfc;
            *(uint4*)&Bs[buf][0][base] = make_uint4(
                pack_bf16(ha0, hb0), pack_bf16(ha1, hb1),
                pack_bf16(ha2, hb2), pack_bf16(ha3, hb3));
            *(uint4*)&Bs[buf][1][base] = make_uint4(
                pack_bf16(va.x - ha0, vb.x - hb0), pack_bf16(va.y - ha1, vb.y - hb1),
                pack_bf16(va.z - ha2, vb.z - hb2), pack_bf16(va.w - ha3, vb.w - hb3));
        }
    };

    loadTile(0);
    storeTile(0);
    __syncthreads();

    for (int t = 0; t < ntiles; t++) {
        if (t + 1 < ntiles) loadTile(t + 1);

        const unsigned* Ash = As[t & 1][0];
        const unsigned* Asl = As[t & 1][1];
        const unsigned* Bsh = Bs[t & 1][0];
        const unsigned* Bsl = Bs[t & 1][1];

        unsigned bh[4][2], bl[4][2];
#pragma unroll
        for (int ns = 0; ns < 4; ns++) {
            const int n = wn + ns * 8 + gid;
            bh[ns][0] = Bsh[tig * BST + n];
            bh[ns][1] = Bsh[(tig + 4) * BST + n];
            bl[ns][0] = Bsl[tig * BST + n];
            bl[ns][1] = Bsl[(tig + 4) * BST + n];
        }
#pragma unroll
        for (int ms = 0; ms < 4; ms++) {
            const int m0 = wm + ms * 16 + gid;
            unsigned ah[4], al[4];
            ah[0] = Ash[m0 * AST + tig];
            ah[1] = Ash[(m0 + 8) * AST + tig];
            ah[2] = Ash[m0 * AST + tig + 4];
            ah[3] = Ash[(m0 + 8) * AST + tig + 4];
            al[0] = Asl[m0 * AST + tig];
            al[1] = Asl[(m0 + 8) * AST + tig];
            al[2] = Asl[m0 * AST + tig + 4];
            al[3] = Asl[(m0 + 8) * AST + tig + 4];
#pragma unroll
            for (int ns = 0; ns < 4; ns++) {
                mma_bf16(acc[ms][ns], ah, bh[ns]);
                mma_bf16(acc[ms][ns], ah, bl[ns]);
                mma_bf16(acc[ms][ns], al, bh[ns]);
            }
        }

        if (t + 1 < ntiles) {
            storeTile((t + 1) & 1);
            __syncthreads();
        }
    }

    const bool hasb   = (bias != nullptr);
    const bool resid  = (flags & 4);
    const bool dorelu = (flags & 5);
#pragma unroll
    for (int ms = 0; ms < 4; ms++) {
        const int r0 = brow + wm + ms * 16 + gid;
        const int r1 = r0 + 8;
        float alive0 = 1.f, alive1 = 1.f;
        const float *E0 = nullptr, *E1 = nullptr;
        if (resid) {
            alive0 = dones[r0] ? 0.f : 1.f;
            alive1 = dones[r1] ? 0.f : 1.f;
            E0 = Ein + (size_t)r0 * N;
            E1 = Ein + (size_t)r1 * N;
        }
#pragma unroll
        for (int ns = 0; ns < 4; ns++) {
            const int c = bcol + wn + ns * 8 + tig * 2;
            float b0 = 0.f, b1 = 0.f;
            if (hasb) { b0 = bias[c]; b1 = bias[c + 1]; }
            float v0 = acc[ms][ns][0] + b0;
            float v1 = acc[ms][ns][1] + b1;
            float v2 = acc[ms][ns][2] + b0;
            float v3 = acc[ms][ns][3] + b1;
            if (dorelu) {
                v0 = fmaxf(v0, 0.f); v1 = fmaxf(v1, 0.f);
                v2 = fmaxf(v2, 0.f); v3 = fmaxf(v3, 0.f);
            }
            if (resid) {
                v0 = (E0[c] + v0) * alive0;     v1 = (E0[c + 1] + v1) * alive0;
                v2 = (E1[c] + v2) * alive1;     v3 = (E1[c + 1] + v3) * alive1;
            }
            *(float2*)&Cout[(size_t)r0 * N + c] = make_float2(v0, v1);
            *(float2*)&Cout[(size_t)r1 * N + c] = make_float2(v2, v3);
        }
    }
}

// ---------------- persistent GRU scan v2: Wh in registers, f32x2 FMA -----------
// 128 blocks x 4 rows; 384 threads, thread tid owns Wh column tid (64 f32x2 regs).
// h stored in smem as [kpair][4 rows] float2 -> broadcast LDS.128 loads.
#define RPB 4
#define GTH 384

__device__ __forceinline__ unsigned long long fma_f32x2(
    unsigned long long a, unsigned long long b, unsigned long long c)
{
    unsigned long long d;
    asm("fma.rn.f32x2 %0, %1, %2, %3;" : "=l"(d) : "l"(a), "l"(b), "l"(c));
    return d;
}

__device__ __forceinline__ float sig_fast(float x)
{
    return __fdividef(1.f, 1.f + __expf(-x));
}
__device__ __forceinline__ float tanh_fast(float x)
{
    return __fdividef(2.f, 1.f + __expf(-2.f * x)) - 1.f;
}

__global__ __launch_bounds__(GTH, 1) void gru_kernel(
    const float* __restrict__ gi,            // (T,B,3D) = x@Wi + bi
    const unsigned char* __restrict__ dones, // (T,B) canonical mask
    const float* __restrict__ h0,            // (B,D)
    const float* __restrict__ Wh,            // (D,3D) row-major
    const float* __restrict__ bhn,           // (D)
    float* __restrict__ e_out,               // (T,B,D) = new_h * alive
    float* __restrict__ hidden_out)          // (B,D)
{
    __shared__ __align__(16) float hs2[64 * 8];   // [kpair][r*2 + (lo/hi)] = h[r][2kp+..]
    __shared__ float ghs[RPB * 384];
    __shared__ float sbhn[D];

    const int tid = threadIdx.x;               // column id 0..383
    const int rowbase = blockIdx.x * RPB;

    // Wh column -> 64 f32x2 registers (coalesced loads across threads)
    unsigned long long w[64];
#pragma unroll
    for (int kp = 0; kp < 64; kp++) {
        const unsigned lo = __float_as_uint(Wh[(size_t)(2 * kp) * 384 + tid]);
        const unsigned hi = __float_as_uint(Wh[(size_t)(2 * kp + 1) * 384 + tid]);
        w[kp] = ((unsigned long long)hi << 32) | lo;
    }
    if (tid < D) sbhn[tid] = bhn[tid];

    // init h (apply dones[0] reset)
    for (int idx = tid; idx < RPB * D; idx += GTH) {
        const int r = idx >> 7, d = idx & 127;
        const int row = rowbase + r;
        float v = dones[row] ? 0.f : h0[(size_t)row * D + d];
        hs2[(d >> 1) * 8 + r * 2 + (d & 1)] = v;
    }
    __syncthreads();

    for (int t = 0; t < T_STEPS; t++) {
        // gh[r][tid] = sum_k h[r][k] * Wh[k][tid]   (f32x2 packed over k-pairs)
        {
            unsigned long long a0 = 0, a1 = 0, a2 = 0, a3 = 0;
#pragma unroll
            for (int kp = 0; kp < 64; kp++) {
                const ulonglong2 p01 = *(const ulonglong2*)(hs2 + kp * 8);
                const ulonglong2 p23 = *(const ulonglong2*)(hs2 + kp * 8 + 4);
                a0 = fma_f32x2(w[kp], p01.x, a0);
                a1 = fma_f32x2(w[kp], p01.y, a1);
                a2 = fma_f32x2(w[kp], p23.x, a2);
                a3 = fma_f32x2(w[kp], p23.y, a3);
            }
            ghs[0 * 384 + tid] = __uint_as_float((unsigned)a0) + __uint_as_float((unsigned)(a0 >> 32));
            ghs[1 * 384 + tid] = __uint_as_float((unsigned)a1) + __uint_as_float((unsigned)(a1 >> 32));
            ghs[2 * 384 + tid] = __uint_as_float((unsigned)a2) + __uint_as_float((unsigned)(a2 >> 32));
            ghs[3 * 384 + tid] = __uint_as_float((unsigned)a3) + __uint_as_float((unsigned)(a3 >> 32));
        }
        __syncthreads();

        // gates; store next-h with dones[t+1] reset folded in
        for (int idx = tid; idx < RPB * D; idx += GTH) {
            const int r = idx >> 7, d = idx & 127;
            const int row = rowbase + r;
            const size_t gib = ((size_t)t * BATCH + row) * (3 * D);
            const float i_r = gi[gib + d];
            const float i_z = gi[gib + D + d];
            const float i_n = gi[gib + 2 * D + d];
            const float h_r = ghs[r * 384 + d];
            const float h_z = ghs[r * 384 + D + d];
            const float h_n = ghs[r * 384 + 2 * D + d];
            const int hsidx = (d >> 1) * 8 + r * 2 + (d & 1);
            const float hprev = hs2[hsidx];
            const float rg = sig_fast(i_r + h_r);
            const float zg = sig_fast(i_z + h_z);
            const float ng = tanh_fast(i_n + rg * (h_n + sbhn[d]));
            const float hn = (1.f - zg) * ng + zg * hprev;
            const float alive = dones[t * BATCH + row] ? 0.f : 1.f;
            e_out[((size_t)t * BATCH + row) * D + d] = hn * alive;
            if (t == T_STEPS - 1) {
                hidden_out[(size_t)row * D + d] = hn;
            } else {
                hs2[hsidx] = dones[(t + 1) * BATCH + row] ? 0.f : hn;
            }
        }
        __syncthreads();
    }
}

// ---------------- fused pairwise-coupling C + context ---------------------------
__global__ __launch_bounds__(256) void couple_ctx_kernel(
    const float* __restrict__ e, const float* __restrict__ aiaj,
    const float* __restrict__ chb,
    const float* __restrict__ cow, const float* __restrict__ cob,
    const unsigned char* __restrict__ dones, float* __restrict__ ctx)
{
    __shared__ float sai[NA * CH], saj[NA * CH], se[NA * D];
    __shared__ float sb[CH], sw[CH];
    __shared__ float sC[NA * NA];
    __shared__ float salive[NA];

    const int g  = blockIdx.x;
    const int t  = g >> 6;
    const int eg = g & 63;
    const size_t base  = (size_t)g * NA * D;
    const size_t base2 = (size_t)g * NA * 256;
    const int tid = threadIdx.x;

#pragma unroll
    for (int q = 0; q < 2; q++) {
        const int idx = (tid + q * 256) * 4;
        const int row = idx >> 8;
        const int col = idx & 255;
        const float4 v = *(const float4*)&aiaj[base2 + idx];
        if (col < 128) *(float4*)&sai[row * 128 + col] = v;
        else           *(float4*)&saj[row * 128 + col - 128] = v;
    }
    *(float4*)&se[tid * 4] = *(const float4*)&e[base + tid * 4];
    if (tid < CH) { sb[tid] = chb[tid]; sw[tid] = cow[tid]; }
    if (tid < NA) salive[tid] = dones[t * BATCH + eg * NA + tid] ? 0.f : 1.f;
    __syncthreads();

    const int warp = tid >> 5, lane = tid & 31;
    {
        const int i = warp;
        const float cb = cob[0];
        for (int j = 0; j < NA; j++) {
            float s = 0.f;
#pragma unroll
            for (int k = lane; k < CH; k += 32) {
                const float v = sai[i * CH + k] + saj[j * CH + k] + sb[k];
                s += fmaxf(v, 0.f) * sw[k];
            }
#pragma unroll
            for (int off = 16; off; off >>= 1) s += __shfl_xor_sync(0xffffffffu, s, off);
            if (lane == 0) {
                const float cv = 1.f / (1.f + expf(-(s + cb)));
                sC[i * NA + j] = (i == j) ? 0.f : cv * salive[j];
            }
        }
    }
    __syncthreads();

    for (int idx = tid; idx < NA * D; idx += 256) {
        const int i = idx >> 7, d = idx & 127;
        float s = 0.f;
#pragma unroll
        for (int j = 0; j < NA; j++) s += sC[i * NA + j] * se[j * D + d];
        ctx[base + idx] = s;
    }
}

// ---------------- final value projection (VH -> 1) ------------------------------
__global__ __launch_bounds__(256) void vout_kernel(
    const float* __restrict__ v2, const float* __restrict__ w,
    const float* __restrict__ b, float* __restrict__ out)
{
    __shared__ float sw[VH];
    const int tid = threadIdx.x;
    sw[tid] = w[tid];
    __syncthreads();
    const int warp = tid >> 5, lane = tid & 31;
    const int row = blockIdx.x * 8 + warp;
    const float* vp = v2 + (size_t)row * VH;
    float s = 0.f;
#pragma unroll
    for (int k = lane; k < VH; k += 32) s += vp[k] * sw[k];
#pragma unroll
    for (int off = 16; off; off >>= 1) s += __shfl_xor_sync(0xffffffffu, s, off);
    if (lane == 0) out[row] = s + b[0];
}

// ---------------- launcher -------------------------------------------------------
extern "C" void kernel_launch(void* const* d_in, const int* in_sizes, int n_in,
                              void* d_out, int out_size)
{
    const float* hidden = (const float*)d_in[0];
    const float* obs    = (const float*)d_in[1];
    const void*  dones_raw = d_in[2];
    const float* e1w = (const float*)d_in[3];
    const float* e1b = (const float*)d_in[4];
    const float* e2w = (const float*)d_in[5];
    const float* e2b = (const float*)d_in[6];
    const float* gWi = (const float*)d_in[7];
    const float* gbi = (const float*)d_in[8];
    const float* gWh = (const float*)d_in[9];
    const float* gbhn = (const float*)d_in[10];
    const float* chw = (const float*)d_in[11];
    const float* chb = (const float*)d_in[12];
    const float* cow = (const float*)d_in[13];
    const float* cob = (const float*)d_in[14];
    const float* uhw = (const float*)d_in[15];
    const float* uhb = (const float*)d_in[16];
    const float* uow = (const float*)d_in[17];
    const float* uob = (const float*)d_in[18];
    const float* v1w = (const float*)d_in[19];
    const float* v1b = (const float*)d_in[20];
    const float* v2w = (const float*)d_in[21];
    const float* v2b = (const float*)d_in[22];
    const float* vow = (const float*)d_in[23];
    const float* vob = (const float*)d_in[24];

    float* out_hidden = (float*)d_out;                 // (B, D)
    float* out_values = (float*)d_out + BATCH * D;     // (T, B)

    float *emb1, *emb2, *gi, *e, *aiaj, *ctx, *d1, *v1, *v2;
    unsigned char* dmask;
    cudaGetSymbolAddress((void**)&emb1, g_emb1);
    cudaGetSymbolAddress((void**)&emb2, g_emb2);
    cudaGetSymbolAddress((void**)&gi,   g_gi);
    cudaGetSymbolAddress((void**)&e,    g_e);
    cudaGetSymbolAddress((void**)&aiaj, g_aiaj);
    cudaGetSymbolAddress((void**)&ctx,  g_ctx);
    cudaGetSymbolAddress((void**)&d1,   g_d1);
    cudaGetSymbolAddress((void**)&v1,   g_v1);
    cudaGetSymbolAddress((void**)&v2,   g_v2);
    cudaGetSymbolAddress((void**)&dmask, g_dmask);

    const int M = TB;
    const dim3 blk(256);

    detect_dones_kernel<<<1, 256>>>((const unsigned char*)dones_raw, TB);
    conv_dones_kernel<<<TB / 256, 256>>>(dones_raw, TB);

    // embed1: relu(obs @ e1w + e1b)
    tgemm_kernel<<<dim3(D / BN, M / BM), blk>>>(M, D, OBS, D, obs, e1w,
        nullptr, nullptr, e1b, emb1, 1, nullptr, nullptr);
    // embed2: relu(emb1 @ e2w + e2b)
    tgemm_kernel<<<dim3(D / BN, M / BM), blk>>>(M, D, D, D, emb1, e2w,
        nullptr, nullptr, e2b, emb2, 1, nullptr, nullptr);
    // gi = emb2 @ gWi + gbi
    tgemm_kernel<<<dim3(3 * D / BN, M / BM), blk>>>(M, 3 * D, D, 3 * D, emb2, gWi,
        nullptr, nullptr, gbi, gi, 0, nullptr, nullptr);
    // sequential GRU scan (register-resident Wh, f32x2 FMA)
    gru_kernel<<<BATCH / RPB, GTH>>>(gi, dmask, hidden, gWh, gbhn, e, out_hidden);

    for (int it = 0; it < ITERS; it++) {
        // [ai | aj] = e @ [W1 | W2]
        tgemm_kernel<<<dim3(2 * CH / BN, M / BM), blk>>>(M, 2 * CH, D, CH, e, chw,
            nullptr, chw + (size_t)D * CH, nullptr, aiaj, 8, nullptr, nullptr);
        couple_ctx_kernel<<<T_STEPS * NE, 256>>>(e, aiaj, chb, cow, cob, dmask, ctx);
        // d1 = relu(e @ U1 + ctx @ U2 + uhb)
        tgemm_kernel<<<dim3(D / BN, M / BM), blk>>>(M, D, D, D, e, uhw,
            ctx, uhw + (size_t)D * D, uhb, d1, 1 | 2, nullptr, nullptr);
        // e = (e + relu(d1 @ uow + uob)) * alive   (in place)
        tgemm_kernel<<<dim3(D / BN, M / BM), blk>>>(M, D, D, D, d1, uow,
            nullptr, nullptr, uob, e, 4, e, dmask);
    }

    // value head
    tgemm_kernel<<<dim3(VH / BN, M / BM), blk>>>(M, VH, D, VH, e, v1w,
        nullptr, nullptr, v1b, v1, 1, nullptr, nullptr);
    tgemm_kernel<<<dim3(VH / BN, M / BM), blk>>>(M, VH, VH, VH, v1, v2w,
        nullptr, nullptr, v2b, v2, 1, nullptr, nullptr);
    vout_kernel<<<TB / 8, 256>>>(v2, vow, vob, out_values);
}

// round 9
// speedup vs baseline: 1.2289x; 1.0958x over previous
#include <cuda_runtime.h>
#include <cuda_bf16.h>
#include <math.h>

#define T_STEPS 128
#define NE 64
#define NA 8
#define OBS 64
#define D 128
#define CH 128
#define VH 256
#define BATCH 512           // NE*NA
#define TB (T_STEPS*BATCH)  // 65536
#define ITERS 2

// ---------------- scratch (static device arrays: allocation-free) -------------
__device__ float g_emb1[TB * D];
__device__ float g_emb2[TB * D];
__device__ float g_gi[TB * 3 * D];
__device__ float g_e[TB * D];
__device__ float g_aiaj[TB * 2 * CH];   // merged [ai | aj], row stride 256
__device__ float g_ctx[TB * D];
__device__ float g_d1[TB * D];
__device__ float g_v1[TB * VH];
__device__ float g_v2[TB * VH];
__device__ unsigned char g_dmask[TB];
__device__ int g_dflag;   // 0 = uint8/bool, 1 = float32, 2 = int32

// ---------------- dones dtype detection + canonicalization --------------------
__global__ void detect_dones_kernel(const unsigned char* __restrict__ p, int n)
{
    __shared__ int s_nonbin, s_off4;
    if (threadIdx.x == 0) { s_nonbin = 0; s_off4 = 0; }
    __syncthreads();
    int nb = 0, o4 = 0;
    for (int i = threadIdx.x; i < n; i += blockDim.x) {
        const unsigned char b = p[i];
        if (b > 1) nb = 1;
        else if (b == 1 && (i & 3)) o4 = 1;
    }
    if (nb) atomicOr(&s_nonbin, 1);
    if (o4) atomicOr(&s_off4, 1);
    __syncthreads();
    if (threadIdx.x == 0)
        g_dflag = s_nonbin ? 1 : (s_off4 ? 0 : 2);
}

__global__ void conv_dones_kernel(const void* __restrict__ p, int n)
{
    const int i = blockIdx.x * blockDim.x + threadIdx.x;
    if (i >= n) return;
    const int f = g_dflag;
    unsigned char m;
    if (f == 1)      m = (((const float*)p)[i] != 0.f);
    else if (f == 2) m = (((const int*)p)[i] != 0);
    else             m = (((const unsigned char*)p)[i] != 0);
    g_dmask[i] = m;
}

// ---------------- TF32 tensor-core GEMM (single product) ----------------------
// C[M,N] = epilogue( A[M,K] @ B[K,N] (+ A2 @ B2) + bias )
// flags: 1 relu | 2 dual-source | 4 resid+alive | 8 B column-split
#define BM 128
#define BN 128
#define BK 16
#define AST 20      // As row stride in u32 (16 used + pad) -> conflict-free frag reads
#define BST 136     // Bs row stride in u32 -> conflict-free frag reads

__device__ __forceinline__ unsigned cvt_tf32(float x)
{
    unsigned u;
    asm("cvt.rna.tf32.f32 %0, %1;" : "=r"(u) : "f"(x));
    return u;
}

__device__ __forceinline__ void mma_tf32(float* c, const unsigned* a, const unsigned* b)
{
    asm volatile(
        "mma.sync.aligned.m16n8k8.row.col.f32.tf32.tf32.f32 "
        "{%0,%1,%2,%3}, {%4,%5,%6,%7}, {%8,%9}, {%0,%1,%2,%3};"
        : "+f"(c[0]), "+f"(c[1]), "+f"(c[2]), "+f"(c[3])
        : "r"(a[0]), "r"(a[1]), "r"(a[2]), "r"(a[3]), "r"(b[0]), "r"(b[1]));
}

__global__ __launch_bounds__(256) void tgemm_kernel(
    int M, int N, int K, int ldb,
    const float* __restrict__ A, const float* __restrict__ Bm,
    const float* __restrict__ A2, const float* __restrict__ B2,
    const float* __restrict__ bias, float* __restrict__ Cout,
    int flags, const float* __restrict__ Ein,
    const unsigned char* __restrict__ dones)
{
    __shared__ __align__(16) unsigned As[2][BM * AST];       // [buf][m][k]
    __shared__ __align__(16) unsigned Bs[2][BK * BST];       // [buf][k][n]

    const int tid  = threadIdx.x;
    const int brow = blockIdx.y * BM;
    const int bcol = blockIdx.x * BN;
    const int w    = tid >> 5, lane = tid & 31;
    const int gid  = lane >> 2, tig = lane & 3;
    const int wm   = (w & 1) * 64;
    const int wn   = (w >> 1) * 32;

    const int arow0 = tid >> 2;          // 0..63 (+64 on pass 1)
    const int afc   = (tid & 3) * 4;     // k-col 0,4,8,12
    const int brw   = tid >> 5;          // k-pair row 0..7
    const int bfc   = (tid & 31) * 4;    // n-col

    float acc[4][4][4];
#pragma unroll
    for (int i = 0; i < 4; i++)
#pragma unroll
        for (int j = 0; j < 4; j++)
#pragma unroll
            for (int q = 0; q < 4; q++) acc[i][j][q] = 0.f;

    const int nsrc = (flags & 2) ? 2 : 1;
    const int tilesPerSrc = K / BK;
    const int ntiles = nsrc * tilesPerSrc;

    float4 rA[2], rB[2];

    auto loadTile = [&](int t) {
        const int s  = (t >= tilesPerSrc) ? 1 : 0;
        const int k0 = (t - s * tilesPerSrc) * BK;
        const float* Ap = s ? A2 : A;
        const float* Bp;
        int bc;
        if (flags & 8) { Bp = (bcol >= BN) ? B2 : Bm; bc = 0; }
        else           { Bp = s ? B2 : Bm;            bc = bcol; }
        rA[0] = *(const float4*)(Ap + (size_t)(brow + arow0) * K + k0 + afc);
        rA[1] = *(const float4*)(Ap + (size_t)(brow + arow0 + 64) * K + k0 + afc);
        rB[0] = *(const float4*)(Bp + (size_t)(k0 + 2 * brw) * ldb + bc + bfc);
        rB[1] = *(const float4*)(Bp + (size_t)(k0 + 2 * brw + 1) * ldb + bc + bfc);
    };

    auto storeTile = [&](int buf) {
#pragma unroll
        for (int p = 0; p < 2; p++) {
            const float4 v = rA[p];
            uint4 o = make_uint4(cvt_tf32(v.x), cvt_tf32(v.y), cvt_tf32(v.z), cvt_tf32(v.w));
            *(uint4*)&As[buf][(arow0 + p * 64) * AST + afc] = o;
        }
        {
            const float4 va = rB[0], vb = rB[1];
            *(uint4*)&Bs[buf][(2 * brw) * BST + bfc] =
                make_uint4(cvt_tf32(va.x), cvt_tf32(va.y), cvt_tf32(va.z), cvt_tf32(va.w));
            *(uint4*)&Bs[buf][(2 * brw + 1) * BST + bfc] =
                make_uint4(cvt_tf32(vb.x), cvt_tf32(vb.y), cvt_tf32(vb.z), cvt_tf32(vb.w));
        }
    };

    loadTile(0);
    storeTile(0);
    __syncthreads();

    for (int t = 0; t < ntiles; t++) {
        if (t + 1 < ntiles) loadTile(t + 1);

        const unsigned* Ash = As[t & 1];
        const unsigned* Bsh = Bs[t & 1];

#pragma unroll
        for (int kc = 0; kc < BK; kc += 8) {
            unsigned bf[4][2];
#pragma unroll
            for (int ns = 0; ns < 4; ns++) {
                const int n = wn + ns * 8 + gid;
                bf[ns][0] = Bsh[(kc + tig) * BST + n];
                bf[ns][1] = Bsh[(kc + tig + 4) * BST + n];
            }
#pragma unroll
            for (int ms = 0; ms < 4; ms++) {
                const int m0 = wm + ms * 16 + gid;
                unsigned af[4];
                af[0] = Ash[m0 * AST + kc + tig];
                af[1] = Ash[(m0 + 8) * AST + kc + tig];
                af[2] = Ash[m0 * AST + kc + tig + 4];
                af[3] = Ash[(m0 + 8) * AST + kc + tig + 4];
#pragma unroll
                for (int ns = 0; ns < 4; ns++)
                    mma_tf32(acc[ms][ns], af, bf[ns]);
            }
        }

        if (t + 1 < ntiles) {
            storeTile((t + 1) & 1);
            __syncthreads();
        }
    }

    const bool hasb   = (bias != nullptr);
    const bool resid  = (flags & 4);
    const bool dorelu = (flags & 5);
#pragma unroll
    for (int ms = 0; ms < 4; ms++) {
        const int r0 = brow + wm + ms * 16 + gid;
        const int r1 = r0 + 8;
        float alive0 = 1.f, alive1 = 1.f;
        const float *E0 = nullptr, *E1 = nullptr;
        if (resid) {
            alive0 = dones[r0] ? 0.f : 1.f;
            alive1 = dones[r1] ? 0.f : 1.f;
            E0 = Ein + (size_t)r0 * N;
            E1 = Ein + (size_t)r1 * N;
        }
#pragma unroll
        for (int ns = 0; ns < 4; ns++) {
            const int c = bcol + wn + ns * 8 + tig * 2;
            float b0 = 0.f, b1 = 0.f;
            if (hasb) { b0 = bias[c]; b1 = bias[c + 1]; }
            float v0 = acc[ms][ns][0] + b0;
            float v1 = acc[ms][ns][1] + b1;
            float v2 = acc[ms][ns][2] + b0;
            float v3 = acc[ms][ns][3] + b1;
            if (dorelu) {
                v0 = fmaxf(v0, 0.f); v1 = fmaxf(v1, 0.f);
                v2 = fmaxf(v2, 0.f); v3 = fmaxf(v3, 0.f);
            }
            if (resid) {
                v0 = (E0[c] + v0) * alive0;     v1 = (E0[c + 1] + v1) * alive0;
                v2 = (E1[c] + v2) * alive1;     v3 = (E1[c + 1] + v3) * alive1;
            }
            *(float2*)&Cout[(size_t)r0 * N + c] = make_float2(v0, v1);
            *(float2*)&Cout[(size_t)r1 * N + c] = make_float2(v2, v3);
        }
    }
}

// ---------------- persistent GRU scan: Wh in registers, f32x2 FMA, gi prefetch -
#define RPB 4
#define GTH 384

__device__ __forceinline__ unsigned long long fma_f32x2(
    unsigned long long a, unsigned long long b, unsigned long long c)
{
    unsigned long long d;
    asm("fma.rn.f32x2 %0, %1, %2, %3;" : "=l"(d) : "l"(a), "l"(b), "l"(c));
    return d;
}

__device__ __forceinline__ float sig_fast(float x)
{
    return __fdividef(1.f, 1.f + __expf(-x));
}
__device__ __forceinline__ float tanh_fast(float x)
{
    return __fdividef(2.f, 1.f + __expf(-2.f * x)) - 1.f;
}

__global__ __launch_bounds__(GTH, 1) void gru_kernel(
    const float* __restrict__ gi,            // (T,B,3D) = x@Wi + bi
    const unsigned char* __restrict__ dones, // (T,B) canonical mask
    const float* __restrict__ h0,            // (B,D)
    const float* __restrict__ Wh,            // (D,3D) row-major
    const float* __restrict__ bhn,           // (D)
    float* __restrict__ e_out,               // (T,B,D) = new_h * alive
    float* __restrict__ hidden_out)          // (B,D)
{
    __shared__ __align__(16) float hs2[64 * 8];   // [kpair][r*2 + (lo/hi)]
    __shared__ float ghs[RPB * 384];
    __shared__ float sbhn[D];

    const int tid = threadIdx.x;               // column id 0..383
    const int rowbase = blockIdx.x * RPB;

    // Wh column -> 64 f32x2 registers
    unsigned long long w[64];
#pragma unroll
    for (int kp = 0; kp < 64; kp++) {
        const unsigned lo = __float_as_uint(Wh[(size_t)(2 * kp) * 384 + tid]);
        const unsigned hi = __float_as_uint(Wh[(size_t)(2 * kp + 1) * 384 + tid]);
        w[kp] = ((unsigned long long)hi << 32) | lo;
    }
    if (tid < D) sbhn[tid] = bhn[tid];

    // item A: idx = tid (rows 0..2); item B: idx = 384 + tid (row 3, tid < 128)
    const int rA = tid >> 7, dA = tid & 127;
    const int rowA = rowbase + rA;
    const bool hasB = (tid < 128);
    const int rowB = rowbase + 3;

    float pa0, pa1, pa2, pb0 = 0.f, pb1 = 0.f, pb2 = 0.f;
    auto prefetch = [&](int t) {
        const size_t gibA = ((size_t)t * BATCH + rowA) * (3 * D);
        pa0 = gi[gibA + dA];
        pa1 = gi[gibA + D + dA];
        pa2 = gi[gibA + 2 * D + dA];
        if (hasB) {
            const size_t gibB = ((size_t)t * BATCH + rowB) * (3 * D);
            pb0 = gi[gibB + tid];
            pb1 = gi[gibB + D + tid];
            pb2 = gi[gibB + 2 * D + tid];
        }
    };

    // init h (apply dones[0] reset)
    for (int idx = tid; idx < RPB * D; idx += GTH) {
        const int r = idx >> 7, d = idx & 127;
        const int row = rowbase + r;
        float v = dones[row] ? 0.f : h0[(size_t)row * D + d];
        hs2[(d >> 1) * 8 + r * 2 + (d & 1)] = v;
    }
    prefetch(0);
    __syncthreads();

    for (int t = 0; t < T_STEPS; t++) {
        // gh[r][tid] = sum_k h[r][k] * Wh[k][tid]   (f32x2 over k-pairs)
        {
            unsigned long long a0 = 0, a1 = 0, a2 = 0, a3 = 0;
#pragma unroll
            for (int kp = 0; kp < 64; kp++) {
                const ulonglong2 p01 = *(const ulonglong2*)(hs2 + kp * 8);
                const ulonglong2 p23 = *(const ulonglong2*)(hs2 + kp * 8 + 4);
                a0 = fma_f32x2(w[kp], p01.x, a0);
                a1 = fma_f32x2(w[kp], p01.y, a1);
                a2 = fma_f32x2(w[kp], p23.x, a2);
                a3 = fma_f32x2(w[kp], p23.y, a3);
            }
            ghs[0 * 384 + tid] = __uint_as_float((unsigned)a0) + __uint_as_float((unsigned)(a0 >> 32));
            ghs[1 * 384 + tid] = __uint_as_float((unsigned)a1) + __uint_as_float((unsigned)(a1 >> 32));
            ghs[2 * 384 + tid] = __uint_as_float((unsigned)a2) + __uint_as_float((unsigned)(a2 >> 32));
            ghs[3 * 384 + tid] = __uint_as_float((unsigned)a3) + __uint_as_float((unsigned)(a3 >> 32));
        }
        __syncthreads();

        // gates with prefetched gi; fold dones[t+1] reset into the h store
        {
            // item A
            {
                const int r = rA, d = dA, row = rowA;
                const float h_r = ghs[r * 384 + d];
                const float h_z = ghs[r * 384 + D + d];
                const float h_n = ghs[r * 384 + 2 * D + d];
                const int hsidx = (d >> 1) * 8 + r * 2 + (d & 1);
                const float hprev = hs2[hsidx];
                const float rg = sig_fast(pa0 + h_r);
                const float zg = sig_fast(pa1 + h_z);
                const float ng = tanh_fast(pa2 + rg * (h_n + sbhn[d]));
                const float hn = (1.f - zg) * ng + zg * hprev;
                const float alive = dones[t * BATCH + row] ? 0.f : 1.f;
                e_out[((size_t)t * BATCH + row) * D + d] = hn * alive;
                if (t == T_STEPS - 1) hidden_out[(size_t)row * D + d] = hn;
                else hs2[hsidx] = dones[(t + 1) * BATCH + row] ? 0.f : hn;
            }
            // item B
            if (hasB) {
                const int r = 3, d = tid, row = rowB;
                const float h_r = ghs[r * 384 + d];
                const float h_z = ghs[r * 384 + D + d];
                const float h_n = ghs[r * 384 + 2 * D + d];
                const int hsidx = (d >> 1) * 8 + r * 2 + (d & 1);
                const float hprev = hs2[hsidx];
                const float rg = sig_fast(pb0 + h_r);
                const float zg = sig_fast(pb1 + h_z);
                const float ng = tanh_fast(pb2 + rg * (h_n + sbhn[d]));
                const float hn = (1.f - zg) * ng + zg * hprev;
                const float alive = dones[t * BATCH + row] ? 0.f : 1.f;
                e_out[((size_t)t * BATCH + row) * D + d] = hn * alive;
                if (t == T_STEPS - 1) hidden_out[(size_t)row * D + d] = hn;
                else hs2[hsidx] = dones[(t + 1) * BATCH + row] ? 0.f : hn;
            }
        }
        if (t + 1 < T_STEPS) prefetch(t + 1);   // LDG latency hides under next gemv
        __syncthreads();
    }
}

// ---------------- fused pairwise-coupling C + context ---------------------------
__global__ __launch_bounds__(256) void couple_ctx_kernel(
    const float* __restrict__ e, const float* __restrict__ aiaj,
    const float* __restrict__ chb,
    const float* __restrict__ cow, const float* __restrict__ cob,
    const unsigned char* __restrict__ dones, float* __restrict__ ctx)
{
    __shared__ float sai[NA * CH], saj[NA * CH], se[NA * D];
    __shared__ float sb[CH], sw[CH];
    __shared__ float sC[NA * NA];
    __shared__ float salive[NA];

    const int g  = blockIdx.x;
    const int t  = g >> 6;
    const int eg = g & 63;
    const size_t base  = (size_t)g * NA * D;
    const size_t base2 = (size_t)g * NA * 256;
    const int tid = threadIdx.x;

#pragma unroll
    for (int q = 0; q < 2; q++) {
        const int idx = (tid + q * 256) * 4;
        const int row = idx >> 8;
        const int col = idx & 255;
        const float4 v = *(const float4*)&aiaj[base2 + idx];
        if (col < 128) *(float4*)&sai[row * 128 + col] = v;
        else           *(float4*)&saj[row * 128 + col - 128] = v;
    }
    *(float4*)&se[tid * 4] = *(const float4*)&e[base + tid * 4];
    if (tid < CH) { sb[tid] = chb[tid]; sw[tid] = cow[tid]; }
    if (tid < NA) salive[tid] = dones[t * BATCH + eg * NA + tid] ? 0.f : 1.f;
    __syncthreads();

    const int warp = tid >> 5, lane = tid & 31;
    {
        const int i = warp;
        const float cb = cob[0];
        for (int j = 0; j < NA; j++) {
            float s = 0.f;
#pragma unroll
            for (int k = lane; k < CH; k += 32) {
                const float v = sai[i * CH + k] + saj[j * CH + k] + sb[k];
                s += fmaxf(v, 0.f) * sw[k];
            }
#pragma unroll
            for (int off = 16; off; off >>= 1) s += __shfl_xor_sync(0xffffffffu, s, off);
            if (lane == 0) {
                const float cv = 1.f / (1.f + expf(-(s + cb)));
                sC[i * NA + j] = (i == j) ? 0.f : cv * salive[j];
            }
        }
    }
    __syncthreads();

    for (int idx = tid; idx < NA * D; idx += 256) {
        const int i = idx >> 7, d = idx & 127;
        float s = 0.f;
#pragma unroll
        for (int j = 0; j < NA; j++) s += sC[i * NA + j] * se[j * D + d];
        ctx[base + idx] = s;
    }
}

// ---------------- final value projection (VH -> 1) ------------------------------
__global__ __launch_bounds__(256) void vout_kernel(
    const float* __restrict__ v2, const float* __restrict__ w,
    const float* __restrict__ b, float* __restrict__ out)
{
    __shared__ float sw[VH];
    const int tid = threadIdx.x;
    sw[tid] = w[tid];
    __syncthreads();
    const int warp = tid >> 5, lane = tid & 31;
    const int row = blockIdx.x * 8 + warp;
    const float* vp = v2 + (size_t)row * VH;
    float s = 0.f;
#pragma unroll
    for (int k = lane; k < VH; k += 32) s += vp[k] * sw[k];
#pragma unroll
    for (int off = 16; off; off >>= 1) s += __shfl_xor_sync(0xffffffffu, s, off);
    if (lane == 0) out[row] = s + b[0];
}

// ---------------- launcher -------------------------------------------------------
extern "C" void kernel_launch(void* const* d_in, const int* in_sizes, int n_in,
                              void* d_out, int out_size)
{
    const float* hidden = (const float*)d_in[0];
    const float* obs    = (const float*)d_in[1];
    const void*  dones_raw = d_in[2];
    const float* e1w = (const float*)d_in[3];
    const float* e1b = (const float*)d_in[4];
    const float* e2w = (const float*)d_in[5];
    const float* e2b = (const float*)d_in[6];
    const float* gWi = (const float*)d_in[7];
    const float* gbi = (const float*)d_in[8];
    const float* gWh = (const float*)d_in[9];
    const float* gbhn = (const float*)d_in[10];
    const float* chw = (const float*)d_in[11];
    const float* chb = (const float*)d_in[12];
    const float* cow = (const float*)d_in[13];
    const float* cob = (const float*)d_in[14];
    const float* uhw = (const float*)d_in[15];
    const float* uhb = (const float*)d_in[16];
    const float* uow = (const float*)d_in[17];
    const float* uob = (const float*)d_in[18];
    const float* v1w = (const float*)d_in[19];
    const float* v1b = (const float*)d_in[20];
    const float* v2w = (const float*)d_in[21];
    const float* v2b = (const float*)d_in[22];
    const float* vow = (const float*)d_in[23];
    const float* vob = (const float*)d_in[24];

    float* out_hidden = (float*)d_out;                 // (B, D)
    float* out_values = (float*)d_out + BATCH * D;     // (T, B)

    float *emb1, *emb2, *gi, *e, *aiaj, *ctx, *d1, *v1, *v2;
    unsigned char* dmask;
    cudaGetSymbolAddress((void**)&emb1, g_emb1);
    cudaGetSymbolAddress((void**)&emb2, g_emb2);
    cudaGetSymbolAddress((void**)&gi,   g_gi);
    cudaGetSymbolAddress((void**)&e,    g_e);
    cudaGetSymbolAddress((void**)&aiaj, g_aiaj);
    cudaGetSymbolAddress((void**)&ctx,  g_ctx);
    cudaGetSymbolAddress((void**)&d1,   g_d1);
    cudaGetSymbolAddress((void**)&v1,   g_v1);
    cudaGetSymbolAddress((void**)&v2,   g_v2);
    cudaGetSymbolAddress((void**)&dmask, g_dmask);

    const int M = TB;
    const dim3 blk(256);

    detect_dones_kernel<<<1, 256>>>((const unsigned char*)dones_raw, TB);
    conv_dones_kernel<<<TB / 256, 256>>>(dones_raw, TB);

    // embed1: relu(obs @ e1w + e1b)
    tgemm_kernel<<<dim3(D / BN, M / BM), blk>>>(M, D, OBS, D, obs, e1w,
        nullptr, nullptr, e1b, emb1, 1, nullptr, nullptr);
    // embed2: relu(emb1 @ e2w + e2b)
    tgemm_kernel<<<dim3(D / BN, M / BM), blk>>>(M, D, D, D, emb1, e2w,
        nullptr, nullptr, e2b, emb2, 1, nullptr, nullptr);
    // gi = emb2 @ gWi + gbi
    tgemm_kernel<<<dim3(3 * D / BN, M / BM), blk>>>(M, 3 * D, D, 3 * D, emb2, gWi,
        nullptr, nullptr, gbi, gi, 0, nullptr, nullptr);
    // sequential GRU scan
    gru_kernel<<<BATCH / RPB, GTH>>>(gi, dmask, hidden, gWh, gbhn, e, out_hidden);

    for (int it = 0; it < ITERS; it++) {
        // [ai | aj] = e @ [W1 | W2]
        tgemm_kernel<<<dim3(2 * CH / BN, M / BM), blk>>>(M, 2 * CH, D, CH, e, chw,
            nullptr, chw + (size_t)D * CH, nullptr, aiaj, 8, nullptr, nullptr);
        couple_ctx_kernel<<<T_STEPS * NE, 256>>>(e, aiaj, chb, cow, cob, dmask, ctx);
        // d1 = relu(e @ U1 + ctx @ U2 + uhb)
        tgemm_kernel<<<dim3(D / BN, M / BM), blk>>>(M, D, D, D, e, uhw,
            ctx, uhw + (size_t)D * D, uhb, d1, 1 | 2, nullptr, nullptr);
        // e = (e + relu(d1 @ uow + uob)) * alive   (in place)
        tgemm_kernel<<<dim3(D / BN, M / BM), blk>>>(M, D, D, D, d1, uow,
            nullptr, nullptr, uob, e, 4, e, dmask);
    }

    // value head
    tgemm_kernel<<<dim3(VH / BN, M / BM), blk>>>(M, VH, D, VH, e, v1w,
        nullptr, nullptr, v1b, v1, 1, nullptr, nullptr);
    tgemm_kernel<<<dim3(VH / BN, M / BM), blk>>>(M, VH, VH, VH, v1, v2w,
        nullptr, nullptr, v2b, v2, 1, nullptr, nullptr);
    vout_kernel<<<TB / 8, 256>>>(v2, vow, vob, out_values);
}